// round 7
// baseline (speedup 1.0000x reference)
#include <cuda_runtime.h>
#include <mma.h>
#include <cstdint>
#include <math.h>

using namespace nvcuda;

#define NMAX 100000
#define EMAX 800000
#define CDIM 128
#define KDIM 256

#define BETA_F 0.6931471805599453f
#define C1_F   0.15342640972002733f

// ---------------- scratch ----------------------------------------------------
__device__ int   g_count[NMAX];
__device__ float g_dis[NMAX];
__device__ int   g_rowstart[NMAX];
__device__ int   g_cursor[NMAX];
__device__ int   g_csr[EMAX];
__device__ int   g_bsum[512];
__device__ int   g_bpre[512];
__device__ int   g_tick;
__device__ float g_h[(size_t)NMAX * CDIM];     // tf32-rounded
__device__ float g_bt[KDIM * CDIM];            // B' = beta*W + C1*[I;I], tf32

// ---------------- helpers ----------------------------------------------------
__device__ __forceinline__ uint32_t cvta_s(const void* p) {
    uint32_t a;
    asm("{ .reg .u64 t; cvta.to.shared.u64 t, %1; cvt.u32.u64 %0, t; }"
        : "=r"(a) : "l"(p));
    return a;
}

__device__ __forceinline__ void cp_async16(uint32_t dst, const void* src,
                                           uint32_t src_bytes) {
    asm volatile("cp.async.ca.shared.global [%0], [%1], 16, %2;"
                 :: "r"(dst), "l"(src), "r"(src_bytes) : "memory");
}

// ---------------- prep: zero counts + build B' -------------------------------
__global__ void k_prep(const float* __restrict__ w1, const float* __restrict__ w2,
                       int n) {
    int i = blockIdx.x * blockDim.x + threadIdx.x;
    if (i < n) g_count[i] = 0;
    if (i < KDIM * CDIM) {
        int nn = i & 127;
        int kk = i >> 7;
        float v = (kk < 128) ? w1[kk * 128 + nn] : w2[(kk - 128) * 128 + nn];
        float b = BETA_F * v;
        if ((kk & 127) == nn) b += C1_F;         // fold C1*(h+x0) into GEMM
        g_bt[i] = wmma::__float_to_tf32(b);
    }
}

__global__ void k_degree(const int* __restrict__ ei, int e) {
    int i = blockIdx.x * blockDim.x + threadIdx.x;
    if (i < e) atomicAdd(&g_count[ei[e + i]], 1);
}

// block sums + dis; last block scans the block sums
__global__ void k_blockscan(int n, int nb) {
    __shared__ int sh[256];
    __shared__ int flag;
    __shared__ int sm[512];
    int t = threadIdx.x;
    int i = blockIdx.x * 256 + t;
    int c = (i < n) ? g_count[i] : 0;
    if (i < n) g_dis[i] = rsqrtf((float)(c + 1));
    sh[t] = c;
    __syncthreads();
#pragma unroll
    for (int off = 128; off > 0; off >>= 1) {
        if (t < off) sh[t] += sh[t + off];
        __syncthreads();
    }
    if (t == 0) {
        g_bsum[blockIdx.x] = sh[0];
        __threadfence();
        int old = atomicAdd(&g_tick, 1);
        flag = (old == nb - 1);
    }
    __syncthreads();
    if (flag) {
        __threadfence();
        sm[t]       = (t < nb)       ? g_bsum[t]       : 0;
        sm[t + 256] = (t + 256 < nb) ? g_bsum[t + 256] : 0;
        __syncthreads();
        for (int off = 1; off < 512; off <<= 1) {
            int a = (t >= off) ? sm[t - off] : 0;
            int b = (t + 256 >= off) ? sm[t + 256 - off] : 0;
            __syncthreads();
            sm[t] += a;
            sm[t + 256] += b;
            __syncthreads();
        }
        if (t < nb)       g_bpre[t]       = (t > 0) ? sm[t - 1] : 0;
        if (t + 256 < nb) g_bpre[t + 256] = sm[t + 255];
        if (t == 0) g_tick = 0;
    }
}

__global__ void k_offsets(int n) {
    __shared__ int sm[256];
    int t = threadIdx.x;
    int i = blockIdx.x * 256 + t;
    int c = (i < n) ? g_count[i] : 0;
    sm[t] = c;
    __syncthreads();
    for (int off = 1; off < 256; off <<= 1) {
        int v = (t >= off) ? sm[t - off] : 0;
        __syncthreads();
        sm[t] += v;
        __syncthreads();
    }
    if (i < n) {
        int excl = sm[t] - c + g_bpre[blockIdx.x];
        g_rowstart[i] = excl;
        g_cursor[i]   = excl;
    }
}

__global__ void k_fill(const int* __restrict__ ei, int e) {
    int i = blockIdx.x * blockDim.x + threadIdx.x;
    if (i < e) {
        int s = ei[i];
        int d = ei[e + i];
        int pos = atomicAdd(&g_cursor[d], 1);
        g_csr[pos] = s;
    }
}

// ---------------- gather SpMM (warp per node, MLP=8) -------------------------
__global__ void k_spmm(const float* __restrict__ x, int n, int e) {
    int warp = (blockIdx.x * blockDim.x + threadIdx.x) >> 5;
    if (warp >= n) return;
    int lane = threadIdx.x & 31;

    const float4* xr = (const float4*)x;
    float di = g_dis[warp];
    float4 a = xr[(size_t)warp * 32 + lane];
    float sn = di * di;
    float4 acc = make_float4(sn * a.x, sn * a.y, sn * a.z, sn * a.w);

    int j   = g_rowstart[warp];
    int end = (warp + 1 < n) ? g_rowstart[warp + 1] : e;

    for (; j + 8 <= end; j += 8) {
        int   ii[8];
        float ww[8];
        float4 vv[8];
#pragma unroll
        for (int q = 0; q < 8; ++q) ii[q] = __ldg(&g_csr[j + q]);
#pragma unroll
        for (int q = 0; q < 8; ++q) ww[q] = di * __ldg(&g_dis[ii[q]]);
#pragma unroll
        for (int q = 0; q < 8; ++q) vv[q] = xr[(size_t)ii[q] * 32 + lane];
#pragma unroll
        for (int q = 0; q < 8; ++q) {
            acc.x += ww[q] * vv[q].x;
            acc.y += ww[q] * vv[q].y;
            acc.z += ww[q] * vv[q].z;
            acc.w += ww[q] * vv[q].w;
        }
    }
    for (; j + 4 <= end; j += 4) {
        int i0 = __ldg(&g_csr[j + 0]);
        int i1 = __ldg(&g_csr[j + 1]);
        int i2 = __ldg(&g_csr[j + 2]);
        int i3 = __ldg(&g_csr[j + 3]);
        float w0 = di * __ldg(&g_dis[i0]);
        float w1 = di * __ldg(&g_dis[i1]);
        float w2 = di * __ldg(&g_dis[i2]);
        float w3 = di * __ldg(&g_dis[i3]);
        float4 v0 = xr[(size_t)i0 * 32 + lane];
        float4 v1 = xr[(size_t)i1 * 32 + lane];
        float4 v2 = xr[(size_t)i2 * 32 + lane];
        float4 v3 = xr[(size_t)i3 * 32 + lane];
        acc.x += w0 * v0.x + w1 * v1.x + w2 * v2.x + w3 * v3.x;
        acc.y += w0 * v0.y + w1 * v1.y + w2 * v2.y + w3 * v3.y;
        acc.z += w0 * v0.z + w1 * v1.z + w2 * v2.z + w3 * v3.z;
        acc.w += w0 * v0.w + w1 * v1.w + w2 * v2.w + w3 * v3.w;
    }
    for (; j < end; ++j) {
        int s = __ldg(&g_csr[j]);
        float w = di * __ldg(&g_dis[s]);
        float4 v = xr[(size_t)s * 32 + lane];
        acc.x += w * v.x; acc.y += w * v.y;
        acc.z += w * v.z; acc.w += w * v.w;
    }
    // pre-round to tf32 so the GEMM A-fragments (h half) need no conversion
    acc.x = wmma::__float_to_tf32(acc.x);
    acc.y = wmma::__float_to_tf32(acc.y);
    acc.z = wmma::__float_to_tf32(acc.z);
    acc.w = wmma::__float_to_tf32(acc.w);
    ((float4*)g_h)[(size_t)warp * 32 + lane] = acc;
}

// ---------------- tf32 WMMA GEMM, cp.async double-buffered -------------------
// out = relu( [h|x0] @ g_bt ),  [N,256]x[256,128]; C1 term folded into g_bt
#define BM 128
#define BN 128
#define BK 32
#define LDA 40
#define LDB 136
#define NT 8

#define STG_A 20480
#define STG_B 17408
#define STG (STG_A + STG_B)
#define GSMEM_BYTES (2 * STG)

__global__ __launch_bounds__(256)
void k_gemm(const float* __restrict__ x0, float* __restrict__ out, int n) {
    extern __shared__ float smem[];
    uint32_t sbase = cvta_s(smem);

    int tid  = threadIdx.x;
    int warp = tid >> 5;
    int bm   = blockIdx.x * BM;
    int wm   = (warp >> 1) * 32;
    int wn   = (warp & 1) * 64;

    int arA = tid >> 3;
    int acA = (tid & 7) * 4;
    int brB = tid >> 5;
    int bcB = (tid & 31) * 4;

    wmma::fragment<wmma::accumulator, 16, 16, 8, float> c[2][4];
#pragma unroll
    for (int i = 0; i < 2; ++i)
#pragma unroll
        for (int jf = 0; jf < 4; ++jf) wmma::fill_fragment(c[i][jf], 0.0f);

    auto issue_stage = [&](int s, int kt) {
        uint32_t aB = sbase + s * STG;
        uint32_t bB = aB + STG_A;
        const float* Ap = (kt < 4) ? g_h : x0;
        int ak0 = (kt & 3) * 32;
#pragma unroll
        for (int q = 0; q < 4; ++q) {
            int r  = arA + 32 * q;
            int gi = bm + r;
            const float* src = Ap + (size_t)gi * CDIM + ak0 + acA;
            cp_async16(aB + (uint32_t)(r * LDA + acA) * 4, src,
                       (gi < n) ? 16u : 0u);
            int kb = brB + 8 * q;
            const float* bsrc = g_bt + (size_t)(kt * 32 + kb) * CDIM + bcB;
            cp_async16(bB + (uint32_t)(kb * LDB + bcB) * 4, bsrc, 16u);
        }
        asm volatile("cp.async.commit_group;" ::: "memory");
    };

    issue_stage(0, 0);

#pragma unroll
    for (int kt = 0; kt < NT; ++kt) {
        if (kt + 1 < NT) {
            issue_stage((kt + 1) & 1, kt + 1);
            asm volatile("cp.async.wait_group 1;" ::: "memory");
        } else {
            asm volatile("cp.async.wait_group 0;" ::: "memory");
        }
        __syncthreads();

        float* sA = smem + (kt & 1) * (STG / 4);
        float* sB = sA + STG_A / 4;

#pragma unroll
        for (int kk = 0; kk < BK; kk += 8) {
            wmma::fragment<wmma::matrix_a, 16, 16, 8, wmma::precision::tf32,
                           wmma::row_major> af[2];
            wmma::fragment<wmma::matrix_b, 16, 16, 8, wmma::precision::tf32,
                           wmma::row_major> bf[4];
#pragma unroll
            for (int i = 0; i < 2; ++i) {
                wmma::load_matrix_sync(af[i], &sA[(wm + 16 * i) * LDA + kk], LDA);
                if (kt >= 4) {   // x0 half needs rounding; h half pre-rounded
#pragma unroll
                    for (int t = 0; t < af[i].num_elements; ++t)
                        af[i].x[t] = wmma::__float_to_tf32(af[i].x[t]);
                }
            }
#pragma unroll
            for (int jf = 0; jf < 4; ++jf)
                wmma::load_matrix_sync(bf[jf], &sB[kk * LDB + wn + 16 * jf], LDB);
#pragma unroll
            for (int i = 0; i < 2; ++i)
#pragma unroll
                for (int jf = 0; jf < 4; ++jf)
                    wmma::mma_sync(c[i][jf], af[i], bf[jf], c[i][jf]);
        }
        __syncthreads();
    }

    // park C, relu, store — no h/x0 re-reads (folded into GEMM)
    float* sC = smem;
#pragma unroll
    for (int i = 0; i < 2; ++i)
#pragma unroll
        for (int jf = 0; jf < 4; ++jf)
            wmma::store_matrix_sync(&sC[(wm + 16 * i) * 128 + wn + 16 * jf],
                                    c[i][jf], 128, wmma::mem_row_major);
    __syncthreads();

    for (int idx = tid; idx < BM * 32; idx += 256) {
        int r  = idx >> 5;
        int c4 = (idx & 31) * 4;
        int gi = bm + r;
        if (gi < n) {
            float4 g = *(float4*)&sC[r * 128 + c4];
            g.x = fmaxf(g.x, 0.f);
            g.y = fmaxf(g.y, 0.f);
            g.z = fmaxf(g.z, 0.f);
            g.w = fmaxf(g.w, 0.f);
            *(float4*)(out + (size_t)gi * CDIM + c4) = g;
        }
    }
}

// ---------------- launch -----------------------------------------------------
extern "C" void kernel_launch(void* const* d_in, const int* in_sizes, int n_in,
                              void* d_out, int out_size) {
    const float* x  = (const float*)d_in[0];
    const float* x0 = (const float*)d_in[1];
    const float* w1 = (const float*)d_in[2];
    const float* w2 = (const float*)d_in[3];
    const int*   ei = (const int*)d_in[4];
    float* out = (float*)d_out;

    int n = in_sizes[0] / CDIM;
    int e = in_sizes[4] / 2;
    int nb = (n + 255) / 256;
    int eb = (e + 255) / 256;

    static int attr_set = 0;
    if (!attr_set) {
        cudaFuncSetAttribute(k_gemm, cudaFuncAttributeMaxDynamicSharedMemorySize,
                             GSMEM_BYTES);
        attr_set = 1;
    }

    k_prep<<<nb, 256>>>(w1, w2, n);
    k_degree<<<eb, 256>>>(ei, e);
    k_blockscan<<<nb, 256>>>(n, nb);
    k_offsets<<<nb, 256>>>(n);
    k_fill<<<eb, 256>>>(ei, e);
    k_spmm<<<(n * 32 + 255) / 256, 256>>>(x, n, e);
    k_gemm<<<(n + BM - 1) / BM, 256, GSMEM_BYTES>>>(x0, out, n);
}

// round 8
// speedup vs baseline: 1.0046x; 1.0046x over previous
#include <cuda_runtime.h>
#include <mma.h>
#include <cstdint>
#include <math.h>

using namespace nvcuda;

#define NMAX 100000
#define EMAX 800000
#define CDIM 128
#define KDIM 256

#define BETA_F 0.6931471805599453f
#define C1_F   0.15342640972002733f

// ---------------- scratch ----------------------------------------------------
__device__ int   g_count[NMAX];
__device__ float g_dis[NMAX];
__device__ int   g_rowstart[NMAX];
__device__ int   g_cursor[NMAX];
__device__ int   g_csr[EMAX];
__device__ int   g_bsum[512];
__device__ int   g_bpre[512];
__device__ int   g_tick;
__device__ float g_h[(size_t)NMAX * CDIM];     // tf32-rounded
__device__ float g_bt[KDIM * CDIM];            // B' = beta*W + C1*[I;I], tf32

// ---------------- helpers ----------------------------------------------------
__device__ __forceinline__ uint32_t cvta_s(const void* p) {
    uint32_t a;
    asm("{ .reg .u64 t; cvta.to.shared.u64 t, %1; cvt.u32.u64 %0, t; }"
        : "=r"(a) : "l"(p));
    return a;
}

__device__ __forceinline__ void cp_async16(uint32_t dst, const void* src,
                                           uint32_t src_bytes) {
    asm volatile("cp.async.ca.shared.global [%0], [%1], 16, %2;"
                 :: "r"(dst), "l"(src), "r"(src_bytes) : "memory");
}

// ---------------- prep: zero counts + build B' -------------------------------
__global__ void k_prep(const float* __restrict__ w1, const float* __restrict__ w2,
                       int n) {
    int i = blockIdx.x * blockDim.x + threadIdx.x;
    if (i < n) g_count[i] = 0;
    if (i < KDIM * CDIM) {
        int nn = i & 127;
        int kk = i >> 7;
        float v = (kk < 128) ? w1[kk * 128 + nn] : w2[(kk - 128) * 128 + nn];
        float b = BETA_F * v;
        if ((kk & 127) == nn) b += C1_F;         // fold C1*(h+x0) into GEMM
        g_bt[i] = wmma::__float_to_tf32(b);
    }
}

__global__ void k_degree(const int* __restrict__ ei, int e) {
    int i = blockIdx.x * blockDim.x + threadIdx.x;
    if (i < e) atomicAdd(&g_count[ei[e + i]], 1);
}

// block sums + dis; last block scans the block sums
__global__ void k_blockscan(int n, int nb) {
    __shared__ int sh[256];
    __shared__ int flag;
    __shared__ int sm[512];
    int t = threadIdx.x;
    int i = blockIdx.x * 256 + t;
    int c = (i < n) ? g_count[i] : 0;
    if (i < n) g_dis[i] = rsqrtf((float)(c + 1));
    sh[t] = c;
    __syncthreads();
#pragma unroll
    for (int off = 128; off > 0; off >>= 1) {
        if (t < off) sh[t] += sh[t + off];
        __syncthreads();
    }
    if (t == 0) {
        g_bsum[blockIdx.x] = sh[0];
        __threadfence();
        int old = atomicAdd(&g_tick, 1);
        flag = (old == nb - 1);
    }
    __syncthreads();
    if (flag) {
        __threadfence();
        sm[t]       = (t < nb)       ? g_bsum[t]       : 0;
        sm[t + 256] = (t + 256 < nb) ? g_bsum[t + 256] : 0;
        __syncthreads();
        for (int off = 1; off < 512; off <<= 1) {
            int a = (t >= off) ? sm[t - off] : 0;
            int b = (t + 256 >= off) ? sm[t + 256 - off] : 0;
            __syncthreads();
            sm[t] += a;
            sm[t + 256] += b;
            __syncthreads();
        }
        if (t < nb)       g_bpre[t]       = (t > 0) ? sm[t - 1] : 0;
        if (t + 256 < nb) g_bpre[t + 256] = sm[t + 255];
        if (t == 0) g_tick = 0;
    }
}

__global__ void k_offsets(int n) {
    __shared__ int sm[256];
    int t = threadIdx.x;
    int i = blockIdx.x * 256 + t;
    int c = (i < n) ? g_count[i] : 0;
    sm[t] = c;
    __syncthreads();
    for (int off = 1; off < 256; off <<= 1) {
        int v = (t >= off) ? sm[t - off] : 0;
        __syncthreads();
        sm[t] += v;
        __syncthreads();
    }
    if (i < n) {
        int excl = sm[t] - c + g_bpre[blockIdx.x];
        g_rowstart[i] = excl;
        g_cursor[i]   = excl;
    }
}

__global__ void k_fill(const int* __restrict__ ei, int e) {
    int i = blockIdx.x * blockDim.x + threadIdx.x;
    if (i < e) {
        int s = ei[i];
        int d = ei[e + i];
        int pos = atomicAdd(&g_cursor[d], 1);
        g_csr[pos] = s;
    }
}

// ---------------- gather SpMM (warp per node, MLP=4) -------------------------
__global__ void k_spmm(const float* __restrict__ x, int n, int e) {
    int warp = (blockIdx.x * blockDim.x + threadIdx.x) >> 5;
    if (warp >= n) return;
    int lane = threadIdx.x & 31;

    const float4* xr = (const float4*)x;
    float di = g_dis[warp];
    float4 a = xr[(size_t)warp * 32 + lane];
    float sn = di * di;
    float4 acc = make_float4(sn * a.x, sn * a.y, sn * a.z, sn * a.w);

    int j   = g_rowstart[warp];
    int end = (warp + 1 < n) ? g_rowstart[warp + 1] : e;

    for (; j + 4 <= end; j += 4) {
        int i0 = __ldg(&g_csr[j + 0]);
        int i1 = __ldg(&g_csr[j + 1]);
        int i2 = __ldg(&g_csr[j + 2]);
        int i3 = __ldg(&g_csr[j + 3]);
        float w0 = di * __ldg(&g_dis[i0]);
        float w1 = di * __ldg(&g_dis[i1]);
        float w2 = di * __ldg(&g_dis[i2]);
        float w3 = di * __ldg(&g_dis[i3]);
        float4 v0 = xr[(size_t)i0 * 32 + lane];
        float4 v1 = xr[(size_t)i1 * 32 + lane];
        float4 v2 = xr[(size_t)i2 * 32 + lane];
        float4 v3 = xr[(size_t)i3 * 32 + lane];
        acc.x += w0 * v0.x + w1 * v1.x + w2 * v2.x + w3 * v3.x;
        acc.y += w0 * v0.y + w1 * v1.y + w2 * v2.y + w3 * v3.y;
        acc.z += w0 * v0.z + w1 * v1.z + w2 * v2.z + w3 * v3.z;
        acc.w += w0 * v0.w + w1 * v1.w + w2 * v2.w + w3 * v3.w;
    }
    for (; j < end; ++j) {
        int s = __ldg(&g_csr[j]);
        float w = di * __ldg(&g_dis[s]);
        float4 v = xr[(size_t)s * 32 + lane];
        acc.x += w * v.x; acc.y += w * v.y;
        acc.z += w * v.z; acc.w += w * v.w;
    }
    // pre-round to tf32 so the GEMM A-fragments (h half) need no conversion
    acc.x = wmma::__float_to_tf32(acc.x);
    acc.y = wmma::__float_to_tf32(acc.y);
    acc.z = wmma::__float_to_tf32(acc.z);
    acc.w = wmma::__float_to_tf32(acc.w);
    ((float4*)g_h)[(size_t)warp * 32 + lane] = acc;
}

// ---------------- tf32 WMMA GEMM, cp.async double-buffered -------------------
// out = relu( [h|x0] @ g_bt ),  [N,256]x[256,128]; C1 term folded into g_bt
#define BM 128
#define BN 128
#define BK 32
#define LDA 40
#define LDB 136
#define NT 8

#define STG_A 20480
#define STG_B 17408
#define STG (STG_A + STG_B)
#define GSMEM_BYTES (2 * STG)

__global__ __launch_bounds__(256)
void k_gemm(const float* __restrict__ x0, float* __restrict__ out, int n) {
    extern __shared__ float smem[];
    uint32_t sbase = cvta_s(smem);

    int tid  = threadIdx.x;
    int warp = tid >> 5;
    int bm   = blockIdx.x * BM;
    int wm   = (warp >> 1) * 32;
    int wn   = (warp & 1) * 64;

    int arA = tid >> 3;
    int acA = (tid & 7) * 4;
    int brB = tid >> 5;
    int bcB = (tid & 31) * 4;

    wmma::fragment<wmma::accumulator, 16, 16, 8, float> c[2][4];
#pragma unroll
    for (int i = 0; i < 2; ++i)
#pragma unroll
        for (int jf = 0; jf < 4; ++jf) wmma::fill_fragment(c[i][jf], 0.0f);

    auto issue_stage = [&](int s, int kt) {
        uint32_t aB = sbase + s * STG;
        uint32_t bB = aB + STG_A;
        const float* Ap = (kt < 4) ? g_h : x0;
        int ak0 = (kt & 3) * 32;
#pragma unroll
        for (int q = 0; q < 4; ++q) {
            int r  = arA + 32 * q;
            int gi = bm + r;
            const float* src = Ap + (size_t)gi * CDIM + ak0 + acA;
            cp_async16(aB + (uint32_t)(r * LDA + acA) * 4, src,
                       (gi < n) ? 16u : 0u);
            int kb = brB + 8 * q;
            const float* bsrc = g_bt + (size_t)(kt * 32 + kb) * CDIM + bcB;
            cp_async16(bB + (uint32_t)(kb * LDB + bcB) * 4, bsrc, 16u);
        }
        asm volatile("cp.async.commit_group;" ::: "memory");
    };

    issue_stage(0, 0);

#pragma unroll
    for (int kt = 0; kt < NT; ++kt) {
        if (kt + 1 < NT) {
            issue_stage((kt + 1) & 1, kt + 1);
            asm volatile("cp.async.wait_group 1;" ::: "memory");
        } else {
            asm volatile("cp.async.wait_group 0;" ::: "memory");
        }
        __syncthreads();

        float* sA = smem + (kt & 1) * (STG / 4);
        float* sB = sA + STG_A / 4;

#pragma unroll
        for (int kk = 0; kk < BK; kk += 8) {
            wmma::fragment<wmma::matrix_a, 16, 16, 8, wmma::precision::tf32,
                           wmma::row_major> af[2];
            wmma::fragment<wmma::matrix_b, 16, 16, 8, wmma::precision::tf32,
                           wmma::row_major> bf[4];
#pragma unroll
            for (int i = 0; i < 2; ++i) {
                wmma::load_matrix_sync(af[i], &sA[(wm + 16 * i) * LDA + kk], LDA);
                if (kt >= 4) {   // x0 half needs rounding; h half pre-rounded
#pragma unroll
                    for (int t = 0; t < af[i].num_elements; ++t)
                        af[i].x[t] = wmma::__float_to_tf32(af[i].x[t]);
                }
            }
#pragma unroll
            for (int jf = 0; jf < 4; ++jf)
                wmma::load_matrix_sync(bf[jf], &sB[kk * LDB + wn + 16 * jf], LDB);
#pragma unroll
            for (int i = 0; i < 2; ++i)
#pragma unroll
                for (int jf = 0; jf < 4; ++jf)
                    wmma::mma_sync(c[i][jf], af[i], bf[jf], c[i][jf]);
        }
        __syncthreads();
    }

    // park C, relu, store — no h/x0 re-reads (folded into GEMM)
    float* sC = smem;
#pragma unroll
    for (int i = 0; i < 2; ++i)
#pragma unroll
        for (int jf = 0; jf < 4; ++jf)
            wmma::store_matrix_sync(&sC[(wm + 16 * i) * 128 + wn + 16 * jf],
                                    c[i][jf], 128, wmma::mem_row_major);
    __syncthreads();

    for (int idx = tid; idx < BM * 32; idx += 256) {
        int r  = idx >> 5;
        int c4 = (idx & 31) * 4;
        int gi = bm + r;
        if (gi < n) {
            float4 g = *(float4*)&sC[r * 128 + c4];
            g.x = fmaxf(g.x, 0.f);
            g.y = fmaxf(g.y, 0.f);
            g.z = fmaxf(g.z, 0.f);
            g.w = fmaxf(g.w, 0.f);
            *(float4*)(out + (size_t)gi * CDIM + c4) = g;
        }
    }
}

// ---------------- launch -----------------------------------------------------
extern "C" void kernel_launch(void* const* d_in, const int* in_sizes, int n_in,
                              void* d_out, int out_size) {
    const float* x  = (const float*)d_in[0];
    const float* x0 = (const float*)d_in[1];
    const float* w1 = (const float*)d_in[2];
    const float* w2 = (const float*)d_in[3];
    const int*   ei = (const int*)d_in[4];
    float* out = (float*)d_out;

    int n = in_sizes[0] / CDIM;
    int e = in_sizes[4] / 2;
    int nb = (n + 255) / 256;
    int eb = (e + 255) / 256;

    static int attr_set = 0;
    if (!attr_set) {
        cudaFuncSetAttribute(k_gemm, cudaFuncAttributeMaxDynamicSharedMemorySize,
                             GSMEM_BYTES);
        attr_set = 1;
    }

    k_prep<<<nb, 256>>>(w1, w2, n);
    k_degree<<<eb, 256>>>(ei, e);
    k_blockscan<<<nb, 256>>>(n, nb);
    k_offsets<<<nb, 256>>>(n);
    k_fill<<<eb, 256>>>(ei, e);
    k_spmm<<<(n * 32 + 255) / 256, 256>>>(x, n, e);
    k_gemm<<<(n + BM - 1) / BM, 256, GSMEM_BYTES>>>(x0, out, n);
}

// round 10
// speedup vs baseline: 1.1835x; 1.1781x over previous
#include <cuda_runtime.h>
#include <cuda_fp16.h>
#include <mma.h>
#include <cstdint>
#include <math.h>

using namespace nvcuda;

#define NMAX 100000
#define EMAX 800000
#define CDIM 128
#define KDIM 256

#define BETA_F 0.6931471805599453f
#define C1_F   0.15342640972002733f

// ---------------- scratch ----------------------------------------------------
__device__ int    g_count[NMAX];
__device__ float  g_dis[NMAX];
__device__ int    g_rowstart[NMAX];
__device__ int    g_cursor[NMAX];
__device__ int    g_csr[EMAX];
__device__ int    g_bsum[512];
__device__ int    g_bpre[512];
__device__ int    g_tick;
__device__ float  g_h[(size_t)NMAX * CDIM];    // tf32-rounded
__device__ float  g_bt[KDIM * CDIM];           // B' = beta*W + C1*[I;I], tf32
__device__ __half g_xh[(size_t)NMAX * CDIM];   // fp16 mirror of x for gather

// ---------------- helpers ----------------------------------------------------
__device__ __forceinline__ uint32_t cvta_s(const void* p) {
    uint32_t a;
    asm("{ .reg .u64 t; cvta.to.shared.u64 t, %1; cvt.u32.u64 %0, t; }"
        : "=r"(a) : "l"(p));
    return a;
}

__device__ __forceinline__ void cp_async16(uint32_t dst, const void* src,
                                           uint32_t src_bytes) {
    asm volatile("cp.async.ca.shared.global [%0], [%1], 16, %2;"
                 :: "r"(dst), "l"(src), "r"(src_bytes) : "memory");
}

__device__ __forceinline__ void acc_row(float4& acc, uint2 r, float w) {
    float2 f0 = __half22float2(*(__half2*)&r.x);
    float2 f1 = __half22float2(*(__half2*)&r.y);
    acc.x += w * f0.x;
    acc.y += w * f0.y;
    acc.z += w * f1.x;
    acc.w += w * f1.y;
}

// ---------------- prep: zero counts + build B' -------------------------------
__global__ void k_prep(const float* __restrict__ w1, const float* __restrict__ w2,
                       int n) {
    int i = blockIdx.x * blockDim.x + threadIdx.x;
    if (i < n) g_count[i] = 0;
    if (i < KDIM * CDIM) {
        int nn = i & 127;
        int kk = i >> 7;
        float v = (kk < 128) ? w1[kk * 128 + nn] : w2[(kk - 128) * 128 + nn];
        float b = BETA_F * v;
        if ((kk & 127) == nn) b += C1_F;         // fold C1*(h+x0) into GEMM
        g_bt[i] = wmma::__float_to_tf32(b);
    }
}

// x (fp32) -> g_xh (fp16), coalesced
__global__ void k_x2h(const float* __restrict__ x, int total4) {
    int i = blockIdx.x * blockDim.x + threadIdx.x;
    if (i < total4) {
        float4 v = ((const float4*)x)[i];
        __half2 a = __floats2half2_rn(v.x, v.y);
        __half2 b = __floats2half2_rn(v.z, v.w);
        uint2 pk;
        pk.x = *(uint32_t*)&a;
        pk.y = *(uint32_t*)&b;
        ((uint2*)g_xh)[i] = pk;
    }
}

__global__ void k_degree(const int* __restrict__ ei, int e) {
    int i = blockIdx.x * blockDim.x + threadIdx.x;
    if (i < e) atomicAdd(&g_count[ei[e + i]], 1);
}

// block sums + dis; last block scans the block sums
__global__ void k_blockscan(int n, int nb) {
    __shared__ int sh[256];
    __shared__ int flag;
    __shared__ int sm[512];
    int t = threadIdx.x;
    int i = blockIdx.x * 256 + t;
    int c = (i < n) ? g_count[i] : 0;
    if (i < n) g_dis[i] = rsqrtf((float)(c + 1));
    sh[t] = c;
    __syncthreads();
#pragma unroll
    for (int off = 128; off > 0; off >>= 1) {
        if (t < off) sh[t] += sh[t + off];
        __syncthreads();
    }
    if (t == 0) {
        g_bsum[blockIdx.x] = sh[0];
        __threadfence();
        int old = atomicAdd(&g_tick, 1);
        flag = (old == nb - 1);
    }
    __syncthreads();
    if (flag) {
        __threadfence();
        sm[t]       = (t < nb)       ? g_bsum[t]       : 0;
        sm[t + 256] = (t + 256 < nb) ? g_bsum[t + 256] : 0;
        __syncthreads();
        for (int off = 1; off < 512; off <<= 1) {
            int a = (t >= off) ? sm[t - off] : 0;
            int b = (t + 256 >= off) ? sm[t + 256 - off] : 0;
            __syncthreads();
            sm[t] += a;
            sm[t + 256] += b;
            __syncthreads();
        }
        if (t < nb)       g_bpre[t]       = (t > 0) ? sm[t - 1] : 0;
        if (t + 256 < nb) g_bpre[t + 256] = sm[t + 255];
        if (t == 0) g_tick = 0;
    }
}

__global__ void k_offsets(int n) {
    __shared__ int sm[256];
    int t = threadIdx.x;
    int i = blockIdx.x * 256 + t;
    int c = (i < n) ? g_count[i] : 0;
    sm[t] = c;
    __syncthreads();
    for (int off = 1; off < 256; off <<= 1) {
        int v = (t >= off) ? sm[t - off] : 0;
        __syncthreads();
        sm[t] += v;
        __syncthreads();
    }
    if (i < n) {
        int excl = sm[t] - c + g_bpre[blockIdx.x];
        g_rowstart[i] = excl;
        g_cursor[i]   = excl;
    }
}

__global__ void k_fill(const int* __restrict__ ei, int e) {
    int i = blockIdx.x * blockDim.x + threadIdx.x;
    if (i < e) {
        int s = ei[i];
        int d = ei[e + i];
        int pos = atomicAdd(&g_cursor[d], 1);
        g_csr[pos] = s;
    }
}

// ---------------- gather SpMM (warp per node, fp16 rows, MLP=4) --------------
__global__ void k_spmm(int n, int e) {
    int warp = (blockIdx.x * blockDim.x + threadIdx.x) >> 5;
    if (warp >= n) return;
    int lane = threadIdx.x & 31;

    const uint2* xh = (const uint2*)g_xh;   // 8B per lane = 4 halfs

    float di = g_dis[warp];
    uint2 sr = xh[(size_t)warp * 32 + lane];
    float sn = di * di;
    float4 acc = make_float4(0.f, 0.f, 0.f, 0.f);
    acc_row(acc, sr, sn);                   // self-loop

    int j   = g_rowstart[warp];
    int end = (warp + 1 < n) ? g_rowstart[warp + 1] : e;

    for (; j + 4 <= end; j += 4) {
        int i0 = __ldg(&g_csr[j + 0]);
        int i1 = __ldg(&g_csr[j + 1]);
        int i2 = __ldg(&g_csr[j + 2]);
        int i3 = __ldg(&g_csr[j + 3]);
        float w0 = di * __ldg(&g_dis[i0]);
        float w1 = di * __ldg(&g_dis[i1]);
        float w2 = di * __ldg(&g_dis[i2]);
        float w3 = di * __ldg(&g_dis[i3]);
        uint2 r0 = xh[(size_t)i0 * 32 + lane];
        uint2 r1 = xh[(size_t)i1 * 32 + lane];
        uint2 r2 = xh[(size_t)i2 * 32 + lane];
        uint2 r3 = xh[(size_t)i3 * 32 + lane];
        acc_row(acc, r0, w0);
        acc_row(acc, r1, w1);
        acc_row(acc, r2, w2);
        acc_row(acc, r3, w3);
    }
    for (; j < end; ++j) {
        int s = __ldg(&g_csr[j]);
        float w = di * __ldg(&g_dis[s]);
        uint2 r = xh[(size_t)s * 32 + lane];
        acc_row(acc, r, w);
    }

    // pre-round to tf32 (GEMM A, h half, consumes without conversion cost)
    acc.x = wmma::__float_to_tf32(acc.x);
    acc.y = wmma::__float_to_tf32(acc.y);
    acc.z = wmma::__float_to_tf32(acc.z);
    acc.w = wmma::__float_to_tf32(acc.w);
    ((float4*)g_h)[(size_t)warp * 32 + lane] = acc;
}

// ---------------- tf32 WMMA GEMM, cp.async double-buffered -------------------
// out = relu( [h|x0] @ g_bt ),  [N,256]x[256,128]; C1 term folded into g_bt
#define BM 128
#define BN 128
#define BK 32
#define LDA 40
#define LDB 136
#define NT 8

#define STG_A 20480
#define STG_B 17408
#define STG (STG_A + STG_B)
#define GSMEM_BYTES (2 * STG)

__global__ __launch_bounds__(256)
void k_gemm(const float* __restrict__ x0, float* __restrict__ out, int n) {
    extern __shared__ float smem[];
    uint32_t sbase = cvta_s(smem);

    int tid  = threadIdx.x;
    int warp = tid >> 5;
    int bm   = blockIdx.x * BM;
    int wm   = (warp >> 1) * 32;
    int wn   = (warp & 1) * 64;

    int arA = tid >> 3;
    int acA = (tid & 7) * 4;
    int brB = tid >> 5;
    int bcB = (tid & 31) * 4;

    wmma::fragment<wmma::accumulator, 16, 16, 8, float> c[2][4];
#pragma unroll
    for (int i = 0; i < 2; ++i)
#pragma unroll
        for (int jf = 0; jf < 4; ++jf) wmma::fill_fragment(c[i][jf], 0.0f);

    auto issue_stage = [&](int s, int kt) {
        uint32_t aB = sbase + s * STG;
        uint32_t bB = aB + STG_A;
        const float* Ap = (kt < 4) ? g_h : x0;
        int ak0 = (kt & 3) * 32;
#pragma unroll
        for (int q = 0; q < 4; ++q) {
            int r  = arA + 32 * q;
            int gi = bm + r;
            const float* src = Ap + (size_t)gi * CDIM + ak0 + acA;
            cp_async16(aB + (uint32_t)(r * LDA + acA) * 4, src,
                       (gi < n) ? 16u : 0u);
            int kb = brB + 8 * q;
            const float* bsrc = g_bt + (size_t)(kt * 32 + kb) * CDIM + bcB;
            cp_async16(bB + (uint32_t)(kb * LDB + bcB) * 4, bsrc, 16u);
        }
        asm volatile("cp.async.commit_group;" ::: "memory");
    };

    issue_stage(0, 0);

    // NOTE: deliberately NOT unrolled (keeps mainloop inside L0 I$; R4-proven)
    for (int kt = 0; kt < NT; ++kt) {
        if (kt + 1 < NT) {
            issue_stage((kt + 1) & 1, kt + 1);
            asm volatile("cp.async.wait_group 1;" ::: "memory");
        } else {
            asm volatile("cp.async.wait_group 0;" ::: "memory");
        }
        __syncthreads();

        float* sA = smem + (kt & 1) * (STG / 4);
        float* sB = sA + STG_A / 4;

#pragma unroll
        for (int kk = 0; kk < BK; kk += 8) {
            wmma::fragment<wmma::matrix_a, 16, 16, 8, wmma::precision::tf32,
                           wmma::row_major> af[2];
            wmma::fragment<wmma::matrix_b, 16, 16, 8, wmma::precision::tf32,
                           wmma::row_major> bf[4];
#pragma unroll
            for (int i = 0; i < 2; ++i) {
                wmma::load_matrix_sync(af[i], &sA[(wm + 16 * i) * LDA + kk], LDA);
#pragma unroll
                for (int t = 0; t < af[i].num_elements; ++t)
                    af[i].x[t] = wmma::__float_to_tf32(af[i].x[t]);
            }
#pragma unroll
            for (int jf = 0; jf < 4; ++jf)
                wmma::load_matrix_sync(bf[jf], &sB[kk * LDB + wn + 16 * jf], LDB);
#pragma unroll
            for (int i = 0; i < 2; ++i)
#pragma unroll
                for (int jf = 0; jf < 4; ++jf)
                    wmma::mma_sync(c[i][jf], af[i], bf[jf], c[i][jf]);
        }
        __syncthreads();
    }

    // park C, relu, store — no h/x0 re-reads (folded into GEMM)
    float* sC = smem;
#pragma unroll
    for (int i = 0; i < 2; ++i)
#pragma unroll
        for (int jf = 0; jf < 4; ++jf)
            wmma::store_matrix_sync(&sC[(wm + 16 * i) * 128 + wn + 16 * jf],
                                    c[i][jf], 128, wmma::mem_row_major);
    __syncthreads();

    for (int idx = tid; idx < BM * 32; idx += 256) {
        int r  = idx >> 5;
        int c4 = (idx & 31) * 4;
        int gi = bm + r;
        if (gi < n) {
            float4 g = *(float4*)&sC[r * 128 + c4];
            g.x = fmaxf(g.x, 0.f);
            g.y = fmaxf(g.y, 0.f);
            g.z = fmaxf(g.z, 0.f);
            g.w = fmaxf(g.w, 0.f);
            *(float4*)(out + (size_t)gi * CDIM + c4) = g;
        }
    }
}

// ---------------- launch -----------------------------------------------------
extern "C" void kernel_launch(void* const* d_in, const int* in_sizes, int n_in,
                              void* d_out, int out_size) {
    const float* x  = (const float*)d_in[0];
    const float* x0 = (const float*)d_in[1];
    const float* w1 = (const float*)d_in[2];
    const float* w2 = (const float*)d_in[3];
    const int*   ei = (const int*)d_in[4];
    float* out = (float*)d_out;

    int n = in_sizes[0] / CDIM;
    int e = in_sizes[4] / 2;
    int nb = (n + 255) / 256;
    int eb = (e + 255) / 256;
    int t4 = n * (CDIM / 4);          // float4 count for x

    static int attr_set = 0;
    if (!attr_set) {
        cudaFuncSetAttribute(k_gemm, cudaFuncAttributeMaxDynamicSharedMemorySize,
                             GSMEM_BYTES);
        attr_set = 1;
    }

    k_prep<<<nb, 256>>>(w1, w2, n);
    k_x2h<<<(t4 + 255) / 256, 256>>>(x, t4);
    k_degree<<<eb, 256>>>(ei, e);
    k_blockscan<<<nb, 256>>>(n, nb);
    k_offsets<<<nb, 256>>>(n);
    k_fill<<<eb, 256>>>(ei, e);
    k_spmm<<<(n * 32 + 255) / 256, 256>>>(n, e);
    k_gemm<<<(n + BM - 1) / BM, 256, GSMEM_BYTES>>>(x0, out, n);
}

// round 11
// speedup vs baseline: 1.8410x; 1.5556x over previous
#include <cuda_runtime.h>
#include <cuda_fp16.h>
#include <mma.h>
#include <cstdint>
#include <math.h>

using namespace nvcuda;

#define NMAX 100000
#define EMAX 800000
#define CDIM 128
#define KDIM 256

#define BETA_F 0.6931471805599453f
#define C1_F   0.15342640972002733f

// ---------------- scratch ----------------------------------------------------
__device__ int    g_count[NMAX];
__device__ float  g_dis[NMAX];
__device__ int    g_rowstart[NMAX];
__device__ int    g_cursor[NMAX];
__device__ int    g_csr[EMAX];
__device__ int    g_bsum[512];
__device__ int    g_bpre[512];
__device__ int    g_tick;
__device__ __half g_xh[(size_t)NMAX * CDIM];   // fp16 mirror of x (gather src)
__device__ __half g_x0h[(size_t)NMAX * CDIM];  // fp16 mirror of x0 (GEMM A)
__device__ __half g_hh[(size_t)NMAX * CDIM];   // h in fp16 (GEMM A)
__device__ __half g_bth[KDIM * CDIM];          // B' = beta*W + C1*[I;I], fp16

// ---------------- helpers ----------------------------------------------------
__device__ __forceinline__ uint32_t cvta_s(const void* p) {
    uint32_t a;
    asm("{ .reg .u64 t; cvta.to.shared.u64 t, %1; cvt.u32.u64 %0, t; }"
        : "=r"(a) : "l"(p));
    return a;
}

__device__ __forceinline__ void cp_async16(uint32_t dst, const void* src,
                                           uint32_t src_bytes) {
    asm volatile("cp.async.ca.shared.global [%0], [%1], 16, %2;"
                 :: "r"(dst), "l"(src), "r"(src_bytes) : "memory");
}

__device__ __forceinline__ void acc_row(float4& acc, uint2 r, float w) {
    float2 f0 = __half22float2(*(__half2*)&r.x);
    float2 f1 = __half22float2(*(__half2*)&r.y);
    acc.x += w * f0.x;
    acc.y += w * f0.y;
    acc.z += w * f1.x;
    acc.w += w * f1.y;
}

// ---------------- prep: zero counts + build B' (fp16) ------------------------
__global__ void k_prep(const float* __restrict__ w1, const float* __restrict__ w2,
                       int n) {
    int i = blockIdx.x * blockDim.x + threadIdx.x;
    if (i < n) g_count[i] = 0;
    if (i < KDIM * CDIM) {
        int nn = i & 127;
        int kk = i >> 7;
        float v = (kk < 128) ? w1[kk * 128 + nn] : w2[(kk - 128) * 128 + nn];
        float b = BETA_F * v;
        if ((kk & 127) == nn) b += C1_F;         // fold C1*(h+x0) into GEMM
        g_bth[i] = __float2half(b);
    }
}

// x, x0 (fp32) -> fp16 mirrors, coalesced
__global__ void k_x2h(const float* __restrict__ x, const float* __restrict__ x0,
                      int t4) {
    int i = blockIdx.x * blockDim.x + threadIdx.x;
    const float* src;
    __half* dst;
    int idx;
    if (i < t4)          { src = x;  dst = g_xh;  idx = i; }
    else if (i < 2 * t4) { src = x0; dst = g_x0h; idx = i - t4; }
    else return;
    float4 v = ((const float4*)src)[idx];
    __half2 a = __floats2half2_rn(v.x, v.y);
    __half2 b = __floats2half2_rn(v.z, v.w);
    uint2 pk;
    pk.x = *(uint32_t*)&a;
    pk.y = *(uint32_t*)&b;
    ((uint2*)dst)[idx] = pk;
}

__global__ void k_degree(const int* __restrict__ ei, int e) {
    int i = blockIdx.x * blockDim.x + threadIdx.x;
    if (i < e) atomicAdd(&g_count[ei[e + i]], 1);
}

// block sums + dis; last block scans the block sums
__global__ void k_blockscan(int n, int nb) {
    __shared__ int sh[256];
    __shared__ int flag;
    __shared__ int sm[512];
    int t = threadIdx.x;
    int i = blockIdx.x * 256 + t;
    int c = (i < n) ? g_count[i] : 0;
    if (i < n) g_dis[i] = rsqrtf((float)(c + 1));
    sh[t] = c;
    __syncthreads();
#pragma unroll
    for (int off = 128; off > 0; off >>= 1) {
        if (t < off) sh[t] += sh[t + off];
        __syncthreads();
    }
    if (t == 0) {
        g_bsum[blockIdx.x] = sh[0];
        __threadfence();
        int old = atomicAdd(&g_tick, 1);
        flag = (old == nb - 1);
    }
    __syncthreads();
    if (flag) {
        __threadfence();
        sm[t]       = (t < nb)       ? g_bsum[t]       : 0;
        sm[t + 256] = (t + 256 < nb) ? g_bsum[t + 256] : 0;
        __syncthreads();
        for (int off = 1; off < 512; off <<= 1) {
            int a = (t >= off) ? sm[t - off] : 0;
            int b = (t + 256 >= off) ? sm[t + 256 - off] : 0;
            __syncthreads();
            sm[t] += a;
            sm[t + 256] += b;
            __syncthreads();
        }
        if (t < nb)       g_bpre[t]       = (t > 0) ? sm[t - 1] : 0;
        if (t + 256 < nb) g_bpre[t + 256] = sm[t + 255];
        if (t == 0) g_tick = 0;
    }
}

__global__ void k_offsets(int n) {
    __shared__ int sm[256];
    int t = threadIdx.x;
    int i = blockIdx.x * 256 + t;
    int c = (i < n) ? g_count[i] : 0;
    sm[t] = c;
    __syncthreads();
    for (int off = 1; off < 256; off <<= 1) {
        int v = (t >= off) ? sm[t - off] : 0;
        __syncthreads();
        sm[t] += v;
        __syncthreads();
    }
    if (i < n) {
        int excl = sm[t] - c + g_bpre[blockIdx.x];
        g_rowstart[i] = excl;
        g_cursor[i]   = excl;
    }
}

__global__ void k_fill(const int* __restrict__ ei, int e) {
    int i = blockIdx.x * blockDim.x + threadIdx.x;
    if (i < e) {
        int s = ei[i];
        int d = ei[e + i];
        int pos = atomicAdd(&g_cursor[d], 1);
        g_csr[pos] = s;
    }
}

// ---------------- gather SpMM (warp per node, fp16 in/out, MLP=4) ------------
__global__ void k_spmm(int n, int e) {
    int warp = (blockIdx.x * blockDim.x + threadIdx.x) >> 5;
    if (warp >= n) return;
    int lane = threadIdx.x & 31;

    const uint2* xh = (const uint2*)g_xh;   // 8B per lane = 4 halfs

    float di = g_dis[warp];
    uint2 sr = xh[(size_t)warp * 32 + lane];
    float sn = di * di;
    float4 acc = make_float4(0.f, 0.f, 0.f, 0.f);
    acc_row(acc, sr, sn);                   // self-loop

    int j   = g_rowstart[warp];
    int end = (warp + 1 < n) ? g_rowstart[warp + 1] : e;

    for (; j + 4 <= end; j += 4) {
        int i0 = __ldg(&g_csr[j + 0]);
        int i1 = __ldg(&g_csr[j + 1]);
        int i2 = __ldg(&g_csr[j + 2]);
        int i3 = __ldg(&g_csr[j + 3]);
        float w0 = di * __ldg(&g_dis[i0]);
        float w1 = di * __ldg(&g_dis[i1]);
        float w2 = di * __ldg(&g_dis[i2]);
        float w3 = di * __ldg(&g_dis[i3]);
        uint2 r0 = xh[(size_t)i0 * 32 + lane];
        uint2 r1 = xh[(size_t)i1 * 32 + lane];
        uint2 r2 = xh[(size_t)i2 * 32 + lane];
        uint2 r3 = xh[(size_t)i3 * 32 + lane];
        acc_row(acc, r0, w0);
        acc_row(acc, r1, w1);
        acc_row(acc, r2, w2);
        acc_row(acc, r3, w3);
    }
    for (; j < end; ++j) {
        int s = __ldg(&g_csr[j]);
        float w = di * __ldg(&g_dis[s]);
        uint2 r = xh[(size_t)s * 32 + lane];
        acc_row(acc, r, w);
    }

    __half2 h0 = __floats2half2_rn(acc.x, acc.y);
    __half2 h1 = __floats2half2_rn(acc.z, acc.w);
    uint2 pk;
    pk.x = *(uint32_t*)&h0;
    pk.y = *(uint32_t*)&h1;
    ((uint2*)g_hh)[(size_t)warp * 32 + lane] = pk;
}

// ---------------- fp16 WMMA GEMM (m16n16k16), cp.async double-buffered -------
// out = relu( [h|x0] @ g_bth ),  [N,256]x[256,128]; C1 term folded into g_bth
#define BM 128
#define BN 128
#define BK 64
#define LDA 72      // halfs (144 B pitch)
#define LDB 136     // halfs (272 B pitch)
#define NT 4

#define STG_A (128 * 72 * 2)   // 18432 B
#define STG_B (64 * 136 * 2)   // 17408 B
#define STG   (STG_A + STG_B)  // 35840 B
#define GSMEM_BYTES (2 * STG)  // 71680 B (C park 64KB reuses this)

__global__ __launch_bounds__(256)
void k_gemm(float* __restrict__ out, int n) {
    extern __shared__ char smemc[];
    uint32_t sbase = cvta_s(smemc);

    int tid  = threadIdx.x;
    int warp = tid >> 5;
    int bm   = blockIdx.x * BM;
    int wm   = (warp >> 1) * 32;      // 0,32,64,96
    int wn   = (warp & 1) * 64;       // 0,64

    // A loader: 128 rows x 64 halfs = 1024 x 16B chunks (4/thread)
    int ar  = tid >> 3;               // 0..31
    int ac8 = (tid & 7) * 8;          // half offset 0..56

    wmma::fragment<wmma::accumulator, 16, 16, 16, float> c[2][4];
#pragma unroll
    for (int i = 0; i < 2; ++i)
#pragma unroll
        for (int jf = 0; jf < 4; ++jf) wmma::fill_fragment(c[i][jf], 0.0f);

    auto issue_stage = [&](int s, int kt) {
        uint32_t aB = sbase + s * STG;
        uint32_t bB = aB + STG_A;
        const __half* Ap = (kt < 2) ? g_hh : g_x0h;
        int k0 = (kt & 1) * 64;
#pragma unroll
        for (int q = 0; q < 4; ++q) {
            int r  = ar + 32 * q;
            int gi = bm + r;
            const __half* src = Ap + (size_t)gi * CDIM + k0 + ac8;
            cp_async16(aB + (uint32_t)(r * LDA + ac8) * 2, src,
                       (gi < n) ? 16u : 0u);
            // B: 64 rows x 128 halfs = 1024 x 16B chunks (4/thread)
            int idx = tid + 256 * q;
            int kb  = idx >> 4;            // 0..63
            int bc8 = (idx & 15) * 8;      // 0..120
            const __half* bsrc = g_bth + (size_t)(kt * 64 + kb) * CDIM + bc8;
            cp_async16(bB + (uint32_t)(kb * LDB + bc8) * 2, bsrc, 16u);
        }
        asm volatile("cp.async.commit_group;" ::: "memory");
    };

    issue_stage(0, 0);

    // deliberately NOT unrolled (L0 I$; R4/R10-proven)
    for (int kt = 0; kt < NT; ++kt) {
        if (kt + 1 < NT) {
            issue_stage((kt + 1) & 1, kt + 1);
            asm volatile("cp.async.wait_group 1;" ::: "memory");
        } else {
            asm volatile("cp.async.wait_group 0;" ::: "memory");
        }
        __syncthreads();

        const __half* sA = (const __half*)(smemc + (kt & 1) * STG);
        const __half* sB = (const __half*)(smemc + (kt & 1) * STG + STG_A);

#pragma unroll
        for (int kk = 0; kk < BK; kk += 16) {
            wmma::fragment<wmma::matrix_a, 16, 16, 16, __half,
                           wmma::row_major> af[2];
            wmma::fragment<wmma::matrix_b, 16, 16, 16, __half,
                           wmma::row_major> bf[4];
#pragma unroll
            for (int i = 0; i < 2; ++i)
                wmma::load_matrix_sync(af[i], &sA[(wm + 16 * i) * LDA + kk], LDA);
#pragma unroll
            for (int jf = 0; jf < 4; ++jf)
                wmma::load_matrix_sync(bf[jf], &sB[kk * LDB + wn + 16 * jf], LDB);
#pragma unroll
            for (int i = 0; i < 2; ++i)
#pragma unroll
                for (int jf = 0; jf < 4; ++jf)
                    wmma::mma_sync(c[i][jf], af[i], bf[jf], c[i][jf]);
        }
        __syncthreads();
    }

    // park C (fp32) in smem, relu, store
    float* sC = (float*)smemc;
#pragma unroll
    for (int i = 0; i < 2; ++i)
#pragma unroll
        for (int jf = 0; jf < 4; ++jf)
            wmma::store_matrix_sync(&sC[(wm + 16 * i) * 128 + wn + 16 * jf],
                                    c[i][jf], 128, wmma::mem_row_major);
    __syncthreads();

    for (int idx = tid; idx < BM * 32; idx += 256) {
        int r  = idx >> 5;
        int c4 = (idx & 31) * 4;
        int gi = bm + r;
        if (gi < n) {
            float4 g = *(float4*)&sC[r * 128 + c4];
            g.x = fmaxf(g.x, 0.f);
            g.y = fmaxf(g.y, 0.f);
            g.z = fmaxf(g.z, 0.f);
            g.w = fmaxf(g.w, 0.f);
            *(float4*)(out + (size_t)gi * CDIM + c4) = g;
        }
    }
}

// ---------------- launch -----------------------------------------------------
extern "C" void kernel_launch(void* const* d_in, const int* in_sizes, int n_in,
                              void* d_out, int out_size) {
    const float* x  = (const float*)d_in[0];
    const float* x0 = (const float*)d_in[1];
    const float* w1 = (const float*)d_in[2];
    const float* w2 = (const float*)d_in[3];
    const int*   ei = (const int*)d_in[4];
    float* out = (float*)d_out;

    int n = in_sizes[0] / CDIM;
    int e = in_sizes[4] / 2;
    int nb = (n + 255) / 256;
    int eb = (e + 255) / 256;
    int t4 = n * (CDIM / 4);          // float4 count per feature matrix

    static int attr_set = 0;
    if (!attr_set) {
        cudaFuncSetAttribute(k_gemm, cudaFuncAttributeMaxDynamicSharedMemorySize,
                             GSMEM_BYTES);
        attr_set = 1;
    }

    k_prep<<<nb, 256>>>(w1, w2, n);
    k_x2h<<<(2 * t4 + 255) / 256, 256>>>(x, x0, t4);
    k_degree<<<eb, 256>>>(ei, e);
    k_blockscan<<<nb, 256>>>(n, nb);
    k_offsets<<<nb, 256>>>(n);
    k_fill<<<eb, 256>>>(ei, e);
    k_spmm<<<(n * 32 + 255) / 256, 256>>>(n, e);
    k_gemm<<<(n + BM - 1) / BM, 256, GSMEM_BYTES>>>(out, n);
}

// round 12
// speedup vs baseline: 1.9014x; 1.0328x over previous
#include <cuda_runtime.h>
#include <cuda_fp16.h>
#include <mma.h>
#include <cstdint>
#include <math.h>

using namespace nvcuda;

#define NMAX 100000
#define EMAX 800000
#define CDIM 128
#define KDIM 256

#define BETA_F 0.6931471805599453f
#define C1_F   0.15342640972002733f

// ---------------- scratch ----------------------------------------------------
__device__ int    g_count[NMAX];
__device__ float  g_dis[NMAX];
__device__ int    g_rowstart[NMAX];
__device__ int    g_cursor[NMAX];
__device__ int    g_csr[EMAX];
__device__ int    g_bsum[512];
__device__ int    g_bpre[512];
__device__ int    g_tick;
__device__ __half g_xh[(size_t)NMAX * CDIM];   // fp16 mirror of x (gather src)
__device__ __half g_x0h[(size_t)NMAX * CDIM];  // fp16 mirror of x0 (GEMM A)
__device__ __half g_hh[(size_t)NMAX * CDIM];   // h in fp16 (GEMM A)
__device__ __half g_bth[KDIM * CDIM];          // B' = beta*W + C1*[I;I], fp16

// ---------------- helpers ----------------------------------------------------
__device__ __forceinline__ uint32_t cvta_s(const void* p) {
    uint32_t a;
    asm("{ .reg .u64 t; cvta.to.shared.u64 t, %1; cvt.u32.u64 %0, t; }"
        : "=r"(a) : "l"(p));
    return a;
}

__device__ __forceinline__ void cp_async16(uint32_t dst, const void* src,
                                           uint32_t src_bytes) {
    asm volatile("cp.async.ca.shared.global [%0], [%1], 16, %2;"
                 :: "r"(dst), "l"(src), "r"(src_bytes) : "memory");
}

__device__ __forceinline__ void acc_row(float4& acc, uint2 r, float w) {
    float2 f0 = __half22float2(*(__half2*)&r.x);
    float2 f1 = __half22float2(*(__half2*)&r.y);
    acc.x += w * f0.x;
    acc.y += w * f0.y;
    acc.z += w * f1.x;
    acc.w += w * f1.y;
}

// ---------------- prep (fused): zero counts + B' + fp16 mirrors --------------
__global__ void k_prep(const float* __restrict__ x, const float* __restrict__ x0,
                       const float* __restrict__ w1, const float* __restrict__ w2,
                       int n, int t4) {
    int i = blockIdx.x * blockDim.x + threadIdx.x;
    if (i < n) g_count[i] = 0;
    if (i < KDIM * CDIM) {
        int nn = i & 127;
        int kk = i >> 7;
        float v = (kk < 128) ? w1[kk * 128 + nn] : w2[(kk - 128) * 128 + nn];
        float b = BETA_F * v;
        if ((kk & 127) == nn) b += C1_F;         // fold C1*(h+x0) into GEMM
        g_bth[i] = __float2half(b);
    }
    const float* src;
    __half* dst;
    int idx;
    if (i < t4)          { src = x;  dst = g_xh;  idx = i; }
    else if (i < 2 * t4) { src = x0; dst = g_x0h; idx = i - t4; }
    else return;
    float4 v = ((const float4*)src)[idx];
    __half2 a = __floats2half2_rn(v.x, v.y);
    __half2 b = __floats2half2_rn(v.z, v.w);
    uint2 pk;
    pk.x = *(uint32_t*)&a;
    pk.y = *(uint32_t*)&b;
    ((uint2*)dst)[idx] = pk;
}

__global__ void k_degree(const int* __restrict__ ei, int e) {
    int i = blockIdx.x * blockDim.x + threadIdx.x;
    if (i < e) atomicAdd(&g_count[ei[e + i]], 1);
}

// block sums + dis; last block scans the block sums
__global__ void k_blockscan(int n, int nb) {
    __shared__ int sh[256];
    __shared__ int flag;
    __shared__ int sm[512];
    int t = threadIdx.x;
    int i = blockIdx.x * 256 + t;
    int c = (i < n) ? g_count[i] : 0;
    if (i < n) g_dis[i] = rsqrtf((float)(c + 1));
    sh[t] = c;
    __syncthreads();
#pragma unroll
    for (int off = 128; off > 0; off >>= 1) {
        if (t < off) sh[t] += sh[t + off];
        __syncthreads();
    }
    if (t == 0) {
        g_bsum[blockIdx.x] = sh[0];
        __threadfence();
        int old = atomicAdd(&g_tick, 1);
        flag = (old == nb - 1);
    }
    __syncthreads();
    if (flag) {
        __threadfence();
        sm[t]       = (t < nb)       ? g_bsum[t]       : 0;
        sm[t + 256] = (t + 256 < nb) ? g_bsum[t + 256] : 0;
        __syncthreads();
        for (int off = 1; off < 512; off <<= 1) {
            int a = (t >= off) ? sm[t - off] : 0;
            int b = (t + 256 >= off) ? sm[t + 256 - off] : 0;
            __syncthreads();
            sm[t] += a;
            sm[t + 256] += b;
            __syncthreads();
        }
        if (t < nb)       g_bpre[t]       = (t > 0) ? sm[t - 1] : 0;
        if (t + 256 < nb) g_bpre[t + 256] = sm[t + 255];
        if (t == 0) g_tick = 0;
    }
}

__global__ void k_offsets(int n) {
    __shared__ int sm[256];
    int t = threadIdx.x;
    int i = blockIdx.x * 256 + t;
    int c = (i < n) ? g_count[i] : 0;
    sm[t] = c;
    __syncthreads();
    for (int off = 1; off < 256; off <<= 1) {
        int v = (t >= off) ? sm[t - off] : 0;
        __syncthreads();
        sm[t] += v;
        __syncthreads();
    }
    if (i < n) {
        int excl = sm[t] - c + g_bpre[blockIdx.x];
        g_rowstart[i] = excl;
        g_cursor[i]   = excl;
    }
}

__global__ void k_fill(const int* __restrict__ ei, int e) {
    int i = blockIdx.x * blockDim.x + threadIdx.x;
    if (i < e) {
        int s = ei[i];
        int d = ei[e + i];
        int pos = atomicAdd(&g_cursor[d], 1);
        g_csr[pos] = s;
    }
}

// ---------------- gather SpMM (warp per node, fp16 in/out, MLP=4) ------------
__global__ void k_spmm(int n, int e) {
    int warp = (blockIdx.x * blockDim.x + threadIdx.x) >> 5;
    if (warp >= n) return;
    int lane = threadIdx.x & 31;

    const uint2* xh = (const uint2*)g_xh;   // 8B per lane = 4 halfs

    float di = g_dis[warp];
    uint2 sr = xh[(size_t)warp * 32 + lane];
    float sn = di * di;
    float4 acc = make_float4(0.f, 0.f, 0.f, 0.f);
    acc_row(acc, sr, sn);                   // self-loop

    int j   = g_rowstart[warp];
    int end = (warp + 1 < n) ? g_rowstart[warp + 1] : e;

    for (; j + 4 <= end; j += 4) {
        int i0 = __ldg(&g_csr[j + 0]);
        int i1 = __ldg(&g_csr[j + 1]);
        int i2 = __ldg(&g_csr[j + 2]);
        int i3 = __ldg(&g_csr[j + 3]);
        float w0 = di * __ldg(&g_dis[i0]);
        float w1 = di * __ldg(&g_dis[i1]);
        float w2 = di * __ldg(&g_dis[i2]);
        float w3 = di * __ldg(&g_dis[i3]);
        uint2 r0 = xh[(size_t)i0 * 32 + lane];
        uint2 r1 = xh[(size_t)i1 * 32 + lane];
        uint2 r2 = xh[(size_t)i2 * 32 + lane];
        uint2 r3 = xh[(size_t)i3 * 32 + lane];
        acc_row(acc, r0, w0);
        acc_row(acc, r1, w1);
        acc_row(acc, r2, w2);
        acc_row(acc, r3, w3);
    }
    for (; j < end; ++j) {
        int s = __ldg(&g_csr[j]);
        float w = di * __ldg(&g_dis[s]);
        uint2 r = xh[(size_t)s * 32 + lane];
        acc_row(acc, r, w);
    }

    __half2 h0 = __floats2half2_rn(acc.x, acc.y);
    __half2 h1 = __floats2half2_rn(acc.z, acc.w);
    uint2 pk;
    pk.x = *(uint32_t*)&h0;
    pk.y = *(uint32_t*)&h1;
    ((uint2*)g_hh)[(size_t)warp * 32 + lane] = pk;
}

// ---------------- fp16 WMMA GEMM (m16n16k16), cp.async double-buffered -------
// out = relu( [h|x0] @ g_bth ),  [N,256]x[256,128]; C1 term folded into g_bth
#define BM 128
#define BN 128
#define BK 64
#define LDA 72      // halfs (144 B pitch)
#define LDB 136     // halfs (272 B pitch)
#define NT 4

#define STG_A (128 * 72 * 2)   // 18432 B
#define STG_B (64 * 136 * 2)   // 17408 B
#define STG   (STG_A + STG_B)  // 35840 B
#define GSMEM_BYTES (2 * STG)  // 71680 B (boundary-block C park reuses this)

__global__ __launch_bounds__(256)
void k_gemm(float* __restrict__ out, int n) {
    extern __shared__ char smemc[];
    uint32_t sbase = cvta_s(smemc);

    int tid  = threadIdx.x;
    int warp = tid >> 5;
    int bm   = blockIdx.x * BM;
    int wm   = (warp >> 1) * 32;      // 0,32,64,96
    int wn   = (warp & 1) * 64;       // 0,64

    int ar  = tid >> 3;               // 0..31
    int ac8 = (tid & 7) * 8;          // half offset 0..56

    wmma::fragment<wmma::accumulator, 16, 16, 16, float> c[2][4];
#pragma unroll
    for (int i = 0; i < 2; ++i)
#pragma unroll
        for (int jf = 0; jf < 4; ++jf) wmma::fill_fragment(c[i][jf], 0.0f);

    auto issue_stage = [&](int s, int kt) {
        uint32_t aB = sbase + s * STG;
        uint32_t bB = aB + STG_A;
        const __half* Ap = (kt < 2) ? g_hh : g_x0h;
        int k0 = (kt & 1) * 64;
#pragma unroll
        for (int q = 0; q < 4; ++q) {
            int r  = ar + 32 * q;
            int gi = bm + r;
            const __half* src = Ap + (size_t)gi * CDIM + k0 + ac8;
            cp_async16(aB + (uint32_t)(r * LDA + ac8) * 2, src,
                       (gi < n) ? 16u : 0u);
            int idx = tid + 256 * q;
            int kb  = idx >> 4;            // 0..63
            int bc8 = (idx & 15) * 8;      // 0..120
            const __half* bsrc = g_bth + (size_t)(kt * 64 + kb) * CDIM + bc8;
            cp_async16(bB + (uint32_t)(kb * LDB + bc8) * 2, bsrc, 16u);
        }
        asm volatile("cp.async.commit_group;" ::: "memory");
    };

    issue_stage(0, 0);

    // deliberately NOT unrolled (L0 I$; R4/R10-proven)
    for (int kt = 0; kt < NT; ++kt) {
        if (kt + 1 < NT) {
            issue_stage((kt + 1) & 1, kt + 1);
            asm volatile("cp.async.wait_group 1;" ::: "memory");
        } else {
            asm volatile("cp.async.wait_group 0;" ::: "memory");
        }
        __syncthreads();

        const __half* sA = (const __half*)(smemc + (kt & 1) * STG);
        const __half* sB = (const __half*)(smemc + (kt & 1) * STG + STG_A);

#pragma unroll
        for (int kk = 0; kk < BK; kk += 16) {
            wmma::fragment<wmma::matrix_a, 16, 16, 16, __half,
                           wmma::row_major> af[2];
            wmma::fragment<wmma::matrix_b, 16, 16, 16, __half,
                           wmma::row_major> bf[4];
#pragma unroll
            for (int i = 0; i < 2; ++i)
                wmma::load_matrix_sync(af[i], &sA[(wm + 16 * i) * LDA + kk], LDA);
#pragma unroll
            for (int jf = 0; jf < 4; ++jf)
                wmma::load_matrix_sync(bf[jf], &sB[kk * LDB + wn + 16 * jf], LDB);
#pragma unroll
            for (int i = 0; i < 2; ++i)
#pragma unroll
                for (int jf = 0; jf < 4; ++jf)
                    wmma::mma_sync(c[i][jf], af[i], bf[jf], c[i][jf]);
        }
        __syncthreads();
    }

    // fragment-level relu
#pragma unroll
    for (int i = 0; i < 2; ++i)
#pragma unroll
        for (int jf = 0; jf < 4; ++jf)
#pragma unroll
            for (int t = 0; t < c[i][jf].num_elements; ++t)
                c[i][jf].x[t] = fmaxf(c[i][jf].x[t], 0.f);

    if (bm + BM <= n) {
        // interior block: store fragments straight to gmem (no smem park)
#pragma unroll
        for (int i = 0; i < 2; ++i)
#pragma unroll
            for (int jf = 0; jf < 4; ++jf)
                wmma::store_matrix_sync(
                    out + (size_t)(bm + wm + 16 * i) * CDIM + wn + 16 * jf,
                    c[i][jf], CDIM, wmma::mem_row_major);
    } else {
        // boundary block: park in smem, masked store
        float* sC = (float*)smemc;
#pragma unroll
        for (int i = 0; i < 2; ++i)
#pragma unroll
            for (int jf = 0; jf < 4; ++jf)
                wmma::store_matrix_sync(&sC[(wm + 16 * i) * 128 + wn + 16 * jf],
                                        c[i][jf], 128, wmma::mem_row_major);
        __syncthreads();
        for (int idx = tid; idx < BM * 32; idx += 256) {
            int r  = idx >> 5;
            int c4 = (idx & 31) * 4;
            int gi = bm + r;
            if (gi < n) {
                float4 g = *(float4*)&sC[r * 128 + c4];
                *(float4*)(out + (size_t)gi * CDIM + c4) = g;
            }
        }
    }
}

// ---------------- launch -----------------------------------------------------
extern "C" void kernel_launch(void* const* d_in, const int* in_sizes, int n_in,
                              void* d_out, int out_size) {
    const float* x  = (const float*)d_in[0];
    const float* x0 = (const float*)d_in[1];
    const float* w1 = (const float*)d_in[2];
    const float* w2 = (const float*)d_in[3];
    const int*   ei = (const int*)d_in[4];
    float* out = (float*)d_out;

    int n = in_sizes[0] / CDIM;
    int e = in_sizes[4] / 2;
    int nb = (n + 255) / 256;
    int eb = (e + 255) / 256;
    int t4 = n * (CDIM / 4);          // float4 count per feature matrix

    static int attr_set = 0;
    if (!attr_set) {
        cudaFuncSetAttribute(k_gemm, cudaFuncAttributeMaxDynamicSharedMemorySize,
                             GSMEM_BYTES);
        attr_set = 1;
    }

    k_prep<<<(2 * t4 + 255) / 256, 256>>>(x, x0, w1, w2, n, t4);
    k_degree<<<eb, 256>>>(ei, e);
    k_blockscan<<<nb, 256>>>(n, nb);
    k_offsets<<<nb, 256>>>(n);
    k_fill<<<eb, 256>>>(ei, e);
    k_spmm<<<(n * 32 + 255) / 256, 256>>>(n, e);
    k_gemm<<<(n + BM - 1) / BM, 256, GSMEM_BYTES>>>(out, n);
}